// round 14
// baseline (speedup 1.0000x reference)
#include <cuda_runtime.h>
#include <stdint.h>
#include <math.h>

// Problem constants (fixed shapes: scores (128, 4096, 2))
#define NN   4096
#define BSZ  128
#define ENS  2
#define BE   256           // BSZ*ENS
#define KK   32
#define NEGC (-1e30f)
#define HALF_OUT 1048576   // 128*4096*2
#define NCHUNK 32
#define CLEN   128         // NN / NCHUNK
#define NSLICE 8
#define SLEN   512         // NN / NSLICE
#define FULLM  0xffffffffu
#define TDEPTH 42          // smem ring depth (>= 41 live rows)
#define TSTR   34          // ring row stride (conflict-free: 2s+l -> 3l mod 32)
#define WTILE  (2 * TDEPTH * TSTR)   // floats per warp (E tile + LQ tile)

// ---------------- scratch (static device memory) ----------------
__device__ float    g_B[(size_t)(NN + 1) * BE * KK]; // B[i][b][j-1]
__device__ unsigned g_mask[(size_t)BE * NN];         // inclusion masks [b*NN + i]
__device__ float    g_CE[(size_t)BE * NCHUNK * KK];  // chunk ESPs
__device__ float    g_BD[(size_t)BE * NCHUNK * KK];  // chunk boundary prefixes
__device__ float    g_M[(size_t)BE * NN];            // unnormalized marginals [b][i]
__device__ float    g_E[(size_t)BE * KK];            // backward state between slices
__device__ float    g_off[BE];                       // log e_31 (early normalizer)
__device__ float    g_logZ[BE];                      // exact log e_32
__device__ unsigned g_bits[(size_t)BE * (NN / 32)];  // sampled bits
// sampler chunk-function tables (chunks 16..127)
__device__ unsigned g_sampBits[(size_t)BE * 128 * 32];
__device__ unsigned g_sampMap[(size_t)BE * 128 * 32];

// ---------------- threefry2x32, key = (0, 42) ----------------
__device__ __forceinline__ uint32_t tf_bits(uint32_t lo)
{
    uint32_t x0 = 0u;
    uint32_t x1 = lo;
    const uint32_t ks0 = 0u, ks1 = 42u, ks2 = 0x1BD11BF0u;
    x0 += ks0; x1 += ks1;
#define TFR(r) { x0 += x1; x1 = (x1 << (r)) | (x1 >> (32 - (r))); x1 ^= x0; }
    TFR(13) TFR(15) TFR(26) TFR(6)   x0 += ks1; x1 += ks2 + 1u;
    TFR(17) TFR(29) TFR(16) TFR(24)  x0 += ks2; x1 += ks0 + 2u;
    TFR(13) TFR(15) TFR(26) TFR(6)   x0 += ks0; x1 += ks1 + 3u;
    TFR(17) TFR(29) TFR(16) TFR(24)  x0 += ks1; x1 += ks2 + 4u;
    TFR(13) TFR(15) TFR(26) TFR(6)   x0 += ks2; x1 += ks0 + 5u;
#undef TFR
    return x0 ^ x1;
}

// EXACT logaddexp (libdevice — bitwise path for sampling masks)
__device__ __forceinline__ float logaddexpf32(float x, float y)
{
    float d = x - y;
    return fmaxf(x, y) + log1pf(expf(-fabsf(d)));
}

// Fast logaddexp (marginals path, 1e-3 tolerance)
__device__ __forceinline__ float logaddexp_fast(float x, float y)
{
    float d = x - y;
    return fmaxf(x, y) + __logf(1.0f + __expf(-fabsf(d)));
}

// ---------------- SKEWED backward slice ----------------
// Lane l runs l warp-steps behind lane 0: at warp-time t, lane l processes
// row i = hi-1-t+l. The cross-lane operand E_{l-1}^{i+1} was produced 2 warp
// steps earlier -> shfl latency falls off the critical path; per-step chain is
// the local exact logaddexp only. Each (i,j) update runs the IDENTICAL fp32
// op sequence on identical operands as the unskewed version -> bit-exact
// g_B / masks. E and logq staged in a smem ring; completed rows flushed with
// a 5-octet lag (coalesced g_B stores + identical expf/ballot mask path).
__device__ void backward_slice(const float* __restrict__ scores, int s,
                               float* tE, float* tQ)
{
    int lane = threadIdx.x & 31;
    int b = blockIdx.x * 4 + (threadIdx.x >> 5);
    const int bz = b >> 1, e = b & 1;
    const float* thbase = scores + (size_t)bz * (NN * ENS) + e;
    const int hi = NN - SLEN * s;   // rows [hi-512, hi), processed descending

    float E;
    if (s == 0) {
        E = NEGC;
        g_B[((size_t)NN * BE + b) * KK + lane] = NEGC;   // init row (i = NN)
    } else {
        E = g_E[(size_t)b * KK + lane];
    }

    // pipeline seeds: lane l's first consumption (t=l) needs E_{l-1}^{hi}
    float Ep1 = __shfl_up_sync(FULLM, E, 1);
    if (lane == 0) Ep1 = 0.0f;
    float Ep2 = 0.0f;              // consumed only by lane 0 at t=0 (e_0 = 0)

    // per-lane theta double buffer: lane l consumes th[hi-1-t+lane]
    float thc[8], thn[8];
#pragma unroll
    for (int d = 0; d < 8; ++d) {
        int i = hi - 1 + lane - d;
        i = min(max(i, 0), NN - 1);
        thc[d] = thbase[2 * i];
    }

    int slot_w = (hi - 1 + lane) % TDEPTH;   // writer ring slot (per lane)
    int slot_f = (hi - 1) % TDEPTH;          // flush ring slot (uniform)
    float uvF = 0.0f;                        // uniforms for current flush 32-block

    // 69 octets: compute octets q=0..67 (t<544=512+32 drain), flush octet m=q-5
    for (int q = 0; q < 69; ++q) {
        if (q < 67) {
#pragma unroll
            for (int d = 0; d < 8; ++d) {
                int i = hi - 1 + lane - 8 * (q + 1) - d;
                i = min(max(i, 0), NN - 1);
                thn[d] = thbase[2 * i];
            }
        }
        int m = q - 5;
        if (m >= 0 && (m & 3) == 0) {
            // refresh uniforms for flush rows [hi-32*(m/4+1), hi-32*(m/4))
            int fb32 = hi - 32 * ((m >> 2) + 1);
            uint32_t rb = tf_bits((uint32_t)((fb32 + lane) * BE + b));
            uvF = fmaxf(__uint_as_float((rb >> 9) | 0x3f800000u) - 1.0f, 0.0f);
        }

#pragma unroll
        for (int d = 0; d < 8; ++d) {
            if (q < 68) {
                int t = q * 8 + d;
                bool active = (t >= lane) && (t < lane + SLEN);
                float shifted = Ep2 + thc[d];                 // E_{l-1}^{i+1} + th_i
                float Enew = logaddexpf32(E, shifted);        // EXACT
                float lqv = shifted - Enew;
                if (active) {
                    E = Enew;
                    tE[slot_w * TSTR + lane] = Enew;
                    tQ[slot_w * TSTR + lane] = lqv;
                }
                slot_w = (slot_w == 0) ? (TDEPTH - 1) : slot_w - 1;
                float sh = __shfl_up_sync(FULLM, E, 1);       // for step t+2
                if (lane == 0) sh = 0.0f;                     // e_0 boundary
                Ep2 = Ep1; Ep1 = sh;
            }
            if (m >= 0) {
                // flush one completed row (9+ steps old -> past a __syncwarp)
                int f = hi - 8 * m - 1 - d;
                float ev  = tE[slot_f * TSTR + lane];
                float lqr = tQ[slot_f * TSTR + lane];
                slot_f = (slot_f == 0) ? (TDEPTH - 1) : slot_f - 1;
                g_B[((size_t)f * BE + b) * KK + lane] = ev;   // coalesced
                float qq = expf(fminf(lqr, 0.0f));            // EXACT mask path
                float u = __shfl_sync(FULLM, uvF, f & 31);
                unsigned mm = __ballot_sync(FULLM, u < qq);
                if (lane == 0) g_mask[(size_t)b * NN + f] = mm;
            }
        }
        __syncwarp();
        if (q < 67) {
#pragma unroll
            for (int d = 0; d < 8; ++d) thc[d] = thn[d];
        }
    }

    if (s < NSLICE - 1) {
        g_E[(size_t)b * KK + lane] = E;      // aligned state at i = hi-512
    } else {
        float lz = __shfl_sync(FULLM, E, 31);   // B[0][b][32] = logZ
        if (lane == 0) g_logZ[b] = lz;
    }
}

// ---------------- sampler chunk-function evaluation (chunks 16..127) ----------------
__device__ void samp_chunk(int xb, int band)
{
    int lane = threadIdx.x & 31;
    int item = xb * 4 + (threadIdx.x >> 5);   // 0..4095
    int b = item >> 4;
    int c = (112 - 16 * band) + (item & 15);

    unsigned mv = g_mask[(size_t)b * NN + c * 32 + lane];  // coalesced
    unsigned r = (unsigned)(lane + 1);
    unsigned w = 0u;
#pragma unroll
    for (int ii = 0; ii < 32; ++ii) {
        unsigned m = __shfl_sync(FULLM, mv, ii);
        unsigned incl = r ? ((m >> (r - 1u)) & 1u) : 0u;
        r -= incl;
        w |= incl << ii;
    }
    g_sampBits[((size_t)b * 128 + c) * 32 + lane] = w;
    g_sampMap[((size_t)b * 128 + c) * 32 + lane] = r;
}

// ---------------- sampler composition (hybrid): warp per b ----------------
__device__ void comp_hybrid(int xb)
{
    int lane = threadIdx.x & 31;
    int b = xb * 4 + (threadIdx.x >> 5);
    const unsigned* mp = &g_sampMap[(size_t)b * 128 * 32];
    const unsigned* bp = &g_sampBits[(size_t)b * 128 * 32];

    unsigned r = KK;   // warp-uniform live state

    // chunks 0..15: inline hypothesis tables from fresh masks
    for (int c = 0; c < 16; ++c) {
        unsigned mv = g_mask[(size_t)b * NN + c * 32 + lane];
        unsigned rr = (unsigned)(lane + 1);
        unsigned w = 0u;
#pragma unroll
        for (int ii = 0; ii < 32; ++ii) {
            unsigned m = __shfl_sync(FULLM, mv, ii);
            unsigned incl = rr ? ((m >> (rr - 1u)) & 1u) : 0u;
            rr -= incl;
            w |= incl << ii;
        }
        unsigned idx = r ? (r - 1u) : 0u;
        unsigned bits = __shfl_sync(FULLM, w, idx);
        unsigned rn   = __shfl_sync(FULLM, rr, idx);
        if (!r) { bits = 0u; rn = 0u; }
        if (lane == 0) g_bits[(size_t)b * 128 + c] = bits;
        r = rn;
    }

    // chunks 16..127: precomputed tables
#pragma unroll 4
    for (int c = 16; c < 128; ++c) {
        unsigned mapv = mp[c * 32 + lane];
        unsigned bitv = bp[c * 32 + lane];
        unsigned idx = r ? (r - 1u) : 0u;
        unsigned bits = __shfl_sync(FULLM, bitv, idx);
        unsigned rn   = __shfl_sync(FULLM, mapv, idx);
        if (!r) { bits = 0u; rn = 0u; }
        if (lane == 0) g_bits[(size_t)b * 128 + c] = bits;
        r = rn;
    }
}

// ---------------- phase A: per-chunk local ESPs ----------------
__device__ void phaseA(const float* __restrict__ scores, int xb)
{
    int lane = threadIdx.x & 31;
    int wid = xb * 4 + (threadIdx.x >> 5);   // 0..8191
    int b = wid >> 5;
    int c = wid & 31;
    const int bz = b >> 1, e = b & 1;
    const float* thbase = scores + (size_t)bz * (NN * ENS) + e;

    float F = (lane == 0) ? 0.0f : NEGC;
    int base0 = c * CLEN;
    for (int blk = 0; blk < CLEN / 32; ++blk) {
        float thv = thbase[2 * (base0 + blk * 32 + lane)];
#pragma unroll 8
        for (int ii = 0; ii < 32; ++ii) {
            float th = __shfl_sync(FULLM, thv, ii);
            float Fp = __shfl_up_sync(FULLM, F, 1);
            if (lane == 0) Fp = NEGC;
            F = logaddexp_fast(F, Fp + th);
        }
    }
    g_CE[((size_t)b * NCHUNK + c) * KK + lane] = F;
}

// ---------------- merge: chunk boundary prefixes + off ----------------
__device__ void merge_chunks(int xb)
{
    int lane = threadIdx.x & 31;
    int b = xb * 4 + (threadIdx.x >> 5);

    float P = (lane == 0) ? 0.0f : NEGC;
    for (int c = 0; c < NCHUNK; ++c) {
        g_BD[((size_t)b * NCHUNK + c) * KK + lane] = P;  // exclusive prefix
        float L = g_CE[((size_t)b * NCHUNK + c) * KK + lane];
        float mx = NEGC;
#pragma unroll
        for (int m = 0; m < 32; ++m) {
            float Pm = __shfl_sync(FULLM, P, m);
            float Lx = __shfl_sync(FULLM, L, (lane - m) & 31);
            if (m <= lane) mx = fmaxf(mx, Pm + Lx);
        }
        float sum = 0.0f;
#pragma unroll
        for (int m = 0; m < 32; ++m) {
            float Pm = __shfl_sync(FULLM, P, m);
            float Lx = __shfl_sync(FULLM, L, (lane - m) & 31);
            if (m <= lane) sum += __expf(Pm + Lx - mx);
        }
        P = mx + __logf(sum);
    }
    if (lane == 31) g_off[b] = P;   // log e_31 — early normalization offset
}

// ---------------- fused phaseC + comb ----------------
__device__ void phaseC_comb(const float* __restrict__ scores, int item,
                            int cbase, int ccnt, float* tile)
{
    int lane = threadIdx.x & 31;
    int b = item / ccnt;
    int c = cbase + (item % ccnt);
    const int bz = b >> 1, e = b & 1;
    const float* thbase = scores + (size_t)bz * (NN * ENS) + e;

    float F = g_BD[((size_t)b * NCHUNK + c) * KK + lane];   // lane j holds log e_j
    float off = g_off[b];
    int base0 = c * CLEN;

    for (int blk = 0; blk < CLEN / 32; ++blk) {
        int base = base0 + blk * 32;
        float thv = thbase[2 * (base + lane)];
#pragma unroll 8
        for (int ii = 0; ii < 32; ++ii) {
            int i = base + ii;
            float Bv = g_B[((size_t)(i + 1) * BE + b) * KK + lane];  // col lane+1
            float th = __shfl_sync(FULLM, thv, ii);
            float Brev = __shfl_sync(FULLM, Bv, (30 - lane) & 31);   // col 31-lane
            if (lane == 31) Brev = 0.0f;                             // col 0 == 0
            tile[ii * 33 + lane] = __expf(F + Brev + (th - off));
            float Fp = __shfl_up_sync(FULLM, F, 1);
            if (lane == 0) Fp = NEGC;
            F = logaddexp_fast(F, Fp + th);
        }
        __syncwarp();
        const float* row = tile + lane * 33;
        float sum = 0.0f;
#pragma unroll
        for (int j = 0; j < 32; ++j) sum += row[j];
        g_M[(size_t)b * NN + base + lane] = sum;
        __syncwarp();
    }
}

// ---------------- sliced fused kernel ----------------
__global__ void k_slice(const float* __restrict__ scores, int s)
{
    __shared__ float s_mem[4 * WTILE];   // 4 warps x (E+LQ rings) = 45.7KB

    int wid = threadIdx.x >> 5;
    if (blockIdx.x < 64) {
        float* tE = &s_mem[wid * WTILE];
        backward_slice(scores, s, tE, tE + TDEPTH * TSTR);
        return;
    }
    int xb = blockIdx.x - 64;
    float* tile = &s_mem[wid * (32 * 33)];   // phaseC tile (first 16.9KB region)

    if (s == 0) {
        phaseA(scores, xb);                               // 2048 blocks
    } else if (s == 1) {
        if (xb < 64) merge_chunks(xb);
        else samp_chunk(xb - 64, 0);                      // 1024 blocks
    } else if (s == 2) {
        if (xb < 512) phaseC_comb(scores, xb * 4 + wid, 24, 8, tile);
        else samp_chunk(xb - 512, 1);
    } else {
        // s = 3..7: phaseC_comb chunks [32-4s, 32-4s+4) + sampler band s-1
        if (xb < 256) phaseC_comb(scores, xb * 4 + wid, 32 - 4 * s, 4, tile);
        else samp_chunk(xb - 256, s - 1);
    }
}

// ---------------- tail: last phaseC_comb band + hybrid composition ----------------
__global__ void k_tail(const float* __restrict__ scores)
{
    __shared__ float s_tile[4][32 * 33];
    if (blockIdx.x < 256) {
        phaseC_comb(scores, blockIdx.x * 4 + (threadIdx.x >> 5), 0, 4,
                    &s_tile[threadIdx.x >> 5][0]);
    } else {
        comp_hybrid(blockIdx.x - 256);   // 64 blocks, warp per b
    }
}

// ---------------- finalize ----------------
__global__ void k_final(float* __restrict__ out)
{
    int tid = blockIdx.x * blockDim.x + threadIdx.x;  // 0 .. 2^20-1
    int bz = tid >> 13;
    int rem = tid & 8191;
    int n = rem >> 1;
    int e = rem & 1;
    int be = bz * ENS + e;
    float s = (float)((g_bits[(size_t)be * (NN / 32) + (n >> 5)] >> (n & 31)) & 1u);
    float m = g_M[(size_t)be * NN + n] * __expf(g_off[be] - g_logZ[be]);
    out[tid] = (s - m) + m;
    out[HALF_OUT + tid] = m;
}

extern "C" void kernel_launch(void* const* d_in, const int* in_sizes, int n_in,
                              void* d_out, int out_size)
{
    const float* scores = (const float*)d_in[0];
    float* out = (float*)d_out;
    (void)in_sizes; (void)n_in; (void)out_size;

    k_slice<<<64 + 2048,       128>>>(scores, 0);  // backward + phaseA
    k_slice<<<64 + 64 + 1024,  128>>>(scores, 1);  // backward + merge + sc b0
    k_slice<<<64 + 512 + 1024, 128>>>(scores, 2);  // backward + PC c24-31 + sc b1
    k_slice<<<64 + 256 + 1024, 128>>>(scores, 3);  // backward + PC c20-23 + sc b2
    k_slice<<<64 + 256 + 1024, 128>>>(scores, 4);  // backward + PC c16-19 + sc b3
    k_slice<<<64 + 256 + 1024, 128>>>(scores, 5);  // backward + PC c12-15 + sc b4
    k_slice<<<64 + 256 + 1024, 128>>>(scores, 6);  // backward + PC c8-11  + sc b5
    k_slice<<<64 + 256 + 1024, 128>>>(scores, 7);  // backward + PC c4-7   + sc b6
    k_tail<<<320, 128>>>(scores);                  // PC c0-3 + hybrid comp
    k_final<<<2048, 512>>>(out);
}

// round 15
// speedup vs baseline: 1.7131x; 1.7131x over previous
#include <cuda_runtime.h>
#include <stdint.h>
#include <math.h>

// Problem constants (fixed shapes: scores (128, 4096, 2))
#define NN   4096
#define BSZ  128
#define ENS  2
#define BE   256           // BSZ*ENS
#define KK   32
#define NEGC (-1e30f)
#define HALF_OUT 1048576   // 128*4096*2
#define NCHUNK 32
#define CLEN   128         // NN / NCHUNK
#define NSLICE 4
#define SLEN   1024        // NN / NSLICE
#define FULLM  0xffffffffu

// ---------------- scratch (static device memory) ----------------
__device__ float    g_B[(size_t)(NN + 1) * BE * KK]; // B[i][b][j-1]
__device__ unsigned g_mask[(size_t)BE * NN];         // inclusion masks [b*NN + i]
__device__ float    g_CE[(size_t)BE * NCHUNK * KK];  // chunk ESPs
__device__ float    g_BD[(size_t)BE * NCHUNK * KK];  // chunk boundary prefixes
__device__ float    g_M[(size_t)BE * NN];            // unnormalized marginals [b][i]
__device__ float    g_E[(size_t)BE * KK];            // backward state between slices
__device__ float    g_off[BE];                       // log e_31 (early normalizer)
__device__ float    g_logZ[BE];                      // exact log e_32
__device__ unsigned g_bits[(size_t)BE * (NN / 32)];  // sampled bits
// sampler chunk-function tables (chunks 32..127)
__device__ unsigned g_sampBits[(size_t)BE * 128 * 32];
__device__ unsigned g_sampMap[(size_t)BE * 128 * 32];

// ---------------- threefry2x32, key = (0, 42) ----------------
__device__ __forceinline__ uint32_t tf_bits(uint32_t lo)
{
    uint32_t x0 = 0u;
    uint32_t x1 = lo;
    const uint32_t ks0 = 0u, ks1 = 42u, ks2 = 0x1BD11BF0u;
    x0 += ks0; x1 += ks1;
#define TFR(r) { x0 += x1; x1 = (x1 << (r)) | (x1 >> (32 - (r))); x1 ^= x0; }
    TFR(13) TFR(15) TFR(26) TFR(6)   x0 += ks1; x1 += ks2 + 1u;
    TFR(17) TFR(29) TFR(16) TFR(24)  x0 += ks2; x1 += ks0 + 2u;
    TFR(13) TFR(15) TFR(26) TFR(6)   x0 += ks0; x1 += ks1 + 3u;
    TFR(17) TFR(29) TFR(16) TFR(24)  x0 += ks1; x1 += ks2 + 4u;
    TFR(13) TFR(15) TFR(26) TFR(6)   x0 += ks2; x1 += ks0 + 5u;
#undef TFR
    return x0 ^ x1;
}

// EXACT logaddexp (libdevice — bitwise path for sampling masks)
__device__ __forceinline__ float logaddexpf32(float x, float y)
{
    float d = x - y;
    return fmaxf(x, y) + log1pf(expf(-fabsf(d)));
}

// Fast logaddexp (marginals path, 1e-3 tolerance)
__device__ __forceinline__ float logaddexp_fast(float x, float y)
{
    float d = x - y;
    return fmaxf(x, y) + __logf(1.0f + __expf(-fabsf(d)));
}

// ---------------- backward slice (exact chain, DEFERRED ballots) ----------------
// R13 chain verbatim; 1024 rows per slice now (32 blocks of 32 steps).
__device__ void backward_slice(const float* __restrict__ scores, int s)
{
    int lane = threadIdx.x & 31;
    int b = blockIdx.x * 4 + (threadIdx.x >> 5);
    const int bz = b >> 1, e = b & 1;
    const float* thbase = scores + (size_t)bz * (NN * ENS) + e;

    float E;
    if (s == 0) {
        E = NEGC;
        g_B[((size_t)NN * BE + b) * KK + lane] = NEGC;   // init row (i = NN)
    } else {
        E = g_E[(size_t)b * KK + lane];
    }

    int blk_hi = (NN / 32) - 32 * s;        // exclusive
    int blk_lo = blk_hi - 32;

    // prefetch theta for the first block of this slice
    float thv = thbase[2 * ((blk_hi - 1) * 32 + lane)];

    for (int blk = blk_hi - 1; blk >= blk_lo; --blk) {
        int base = blk * 32;
        float thv_next = (blk > blk_lo) ? thbase[2 * ((blk - 1) * 32 + lane)] : 0.0f;
        // inline threefry uniform (bit-identical to jax.random.uniform, index i*BE+b)
        uint32_t rb = tf_bits((uint32_t)((base + lane) * BE + b));
        float uv = fmaxf(__uint_as_float((rb >> 9) | 0x3f800000u) - 1.0f, 0.0f);

#pragma unroll
        for (int g8 = 3; g8 >= 0; --g8) {
            float lq[8];
            // chain segment: 8 exact steps; ballots deferred (off critical path)
#pragma unroll
            for (int t = 7; t >= 0; --t) {
                int ii = g8 * 8 + t;
                float th = __shfl_sync(FULLM, thv, ii);
                float Ep = __shfl_up_sync(FULLM, E, 1);
                if (lane == 0) Ep = 0.0f;
                float shifted = Ep + th;
                float Enew = logaddexpf32(E, shifted);
                lq[t] = shifted - Enew;       // logq, buffered
                E = Enew;
                g_B[((size_t)(base + ii) * BE + b) * KK + lane] = E;
            }
            // deferred mask generation: 8 independent expf+ballot, pipelined
#pragma unroll
            for (int t = 7; t >= 0; --t) {
                int ii = g8 * 8 + t;
                float u = __shfl_sync(FULLM, uv, ii);
                float q = expf(fminf(lq[t], 0.0f));
                unsigned m = __ballot_sync(FULLM, u < q);
                if (lane == 0) g_mask[(size_t)b * NN + base + ii] = m;
            }
        }
        thv = thv_next;
    }

    if (s < NSLICE - 1) {
        g_E[(size_t)b * KK + lane] = E;
    } else {
        float lz = __shfl_sync(FULLM, E, 31);   // B[0][b][32] = logZ
        if (lane == 0) g_logZ[b] = lz;
    }
}

// ---------------- sampler chunk-function evaluation (32-chunk bands) ----------------
__device__ void samp_chunk(int xb, int cbase)
{
    int lane = threadIdx.x & 31;
    int item = xb * 4 + (threadIdx.x >> 5);   // 0..8191
    int b = item >> 5;
    int c = cbase + (item & 31);

    unsigned mv = g_mask[(size_t)b * NN + c * 32 + lane];  // coalesced
    unsigned r = (unsigned)(lane + 1);
    unsigned w = 0u;
#pragma unroll
    for (int ii = 0; ii < 32; ++ii) {
        unsigned m = __shfl_sync(FULLM, mv, ii);
        unsigned incl = r ? ((m >> (r - 1u)) & 1u) : 0u;
        r -= incl;
        w |= incl << ii;
    }
    g_sampBits[((size_t)b * 128 + c) * 32 + lane] = w;
    g_sampMap[((size_t)b * 128 + c) * 32 + lane] = r;
}

// ---------------- sampler composition (hybrid): warp per b ----------------
// Chunks 0..31 inlined from fresh masks (slice 3); chunks 32..127 from tables.
__device__ void comp_hybrid(int xb)
{
    int lane = threadIdx.x & 31;
    int b = xb * 4 + (threadIdx.x >> 5);
    const unsigned* mp = &g_sampMap[(size_t)b * 128 * 32];
    const unsigned* bp = &g_sampBits[(size_t)b * 128 * 32];

    unsigned r = KK;   // warp-uniform live state

    for (int c = 0; c < 32; ++c) {
        unsigned mv = g_mask[(size_t)b * NN + c * 32 + lane];
        unsigned rr = (unsigned)(lane + 1);
        unsigned w = 0u;
#pragma unroll
        for (int ii = 0; ii < 32; ++ii) {
            unsigned m = __shfl_sync(FULLM, mv, ii);
            unsigned incl = rr ? ((m >> (rr - 1u)) & 1u) : 0u;
            rr -= incl;
            w |= incl << ii;
        }
        unsigned idx = r ? (r - 1u) : 0u;
        unsigned bits = __shfl_sync(FULLM, w, idx);
        unsigned rn   = __shfl_sync(FULLM, rr, idx);
        if (!r) { bits = 0u; rn = 0u; }
        if (lane == 0) g_bits[(size_t)b * 128 + c] = bits;
        r = rn;
    }

#pragma unroll 4
    for (int c = 32; c < 128; ++c) {
        unsigned mapv = mp[c * 32 + lane];
        unsigned bitv = bp[c * 32 + lane];
        unsigned idx = r ? (r - 1u) : 0u;
        unsigned bits = __shfl_sync(FULLM, bitv, idx);
        unsigned rn   = __shfl_sync(FULLM, mapv, idx);
        if (!r) { bits = 0u; rn = 0u; }
        if (lane == 0) g_bits[(size_t)b * 128 + c] = bits;
        r = rn;
    }
}

// ---------------- phase A: per-chunk local ESPs ----------------
__device__ void phaseA(const float* __restrict__ scores, int xb)
{
    int lane = threadIdx.x & 31;
    int wid = xb * 4 + (threadIdx.x >> 5);   // 0..8191
    int b = wid >> 5;
    int c = wid & 31;
    const int bz = b >> 1, e = b & 1;
    const float* thbase = scores + (size_t)bz * (NN * ENS) + e;

    float F = (lane == 0) ? 0.0f : NEGC;
    int base0 = c * CLEN;
    for (int blk = 0; blk < CLEN / 32; ++blk) {
        float thv = thbase[2 * (base0 + blk * 32 + lane)];
#pragma unroll 8
        for (int ii = 0; ii < 32; ++ii) {
            float th = __shfl_sync(FULLM, thv, ii);
            float Fp = __shfl_up_sync(FULLM, F, 1);
            if (lane == 0) Fp = NEGC;
            F = logaddexp_fast(F, Fp + th);
        }
    }
    g_CE[((size_t)b * NCHUNK + c) * KK + lane] = F;
}

// ---------------- merge: chunk boundary prefixes + off ----------------
__device__ void merge_chunks(int xb)
{
    int lane = threadIdx.x & 31;
    int b = xb * 4 + (threadIdx.x >> 5);

    float P = (lane == 0) ? 0.0f : NEGC;
    for (int c = 0; c < NCHUNK; ++c) {
        g_BD[((size_t)b * NCHUNK + c) * KK + lane] = P;  // exclusive prefix
        float L = g_CE[((size_t)b * NCHUNK + c) * KK + lane];
        float mx = NEGC;
#pragma unroll
        for (int m = 0; m < 32; ++m) {
            float Pm = __shfl_sync(FULLM, P, m);
            float Lx = __shfl_sync(FULLM, L, (lane - m) & 31);
            if (m <= lane) mx = fmaxf(mx, Pm + Lx);
        }
        float sum = 0.0f;
#pragma unroll
        for (int m = 0; m < 32; ++m) {
            float Pm = __shfl_sync(FULLM, P, m);
            float Lx = __shfl_sync(FULLM, L, (lane - m) & 31);
            if (m <= lane) sum += __expf(Pm + Lx - mx);
        }
        P = mx + __logf(sum);
    }
    if (lane == 31) g_off[b] = P;   // log e_31 — early normalization offset
}

// ---------------- fused phaseC + comb ----------------
__device__ void phaseC_comb(const float* __restrict__ scores, int item,
                            int cbase, int ccnt, float* tile)
{
    int lane = threadIdx.x & 31;
    int b = item / ccnt;
    int c = cbase + (item % ccnt);
    const int bz = b >> 1, e = b & 1;
    const float* thbase = scores + (size_t)bz * (NN * ENS) + e;

    float F = g_BD[((size_t)b * NCHUNK + c) * KK + lane];   // lane j holds log e_j
    float off = g_off[b];
    int base0 = c * CLEN;

    for (int blk = 0; blk < CLEN / 32; ++blk) {
        int base = base0 + blk * 32;
        float thv = thbase[2 * (base + lane)];
#pragma unroll 8
        for (int ii = 0; ii < 32; ++ii) {
            int i = base + ii;
            float Bv = g_B[((size_t)(i + 1) * BE + b) * KK + lane];  // col lane+1
            float th = __shfl_sync(FULLM, thv, ii);
            float Brev = __shfl_sync(FULLM, Bv, (30 - lane) & 31);   // col 31-lane
            if (lane == 31) Brev = 0.0f;                             // col 0 == 0
            tile[ii * 33 + lane] = __expf(F + Brev + (th - off));
            float Fp = __shfl_up_sync(FULLM, F, 1);
            if (lane == 0) Fp = NEGC;
            F = logaddexp_fast(F, Fp + th);
        }
        __syncwarp();
        const float* row = tile + lane * 33;
        float sum = 0.0f;
#pragma unroll
        for (int j = 0; j < 32; ++j) sum += row[j];
        g_M[(size_t)b * NN + base + lane] = sum;
        __syncwarp();
    }
}

// ---------------- sliced fused kernel ----------------
__global__ void k_slice(const float* __restrict__ scores, int s)
{
    __shared__ float s_tile[4][32 * 33];   // 16.9KB; only phaseC_comb uses it

    if (blockIdx.x < 64) {
        backward_slice(scores, s);
        return;
    }
    int xb = blockIdx.x - 64;
    int wid = threadIdx.x >> 5;
    float* tile = &s_tile[wid][0];

    if (s == 0) {
        phaseA(scores, xb);                               // 2048 blocks
    } else if (s == 1) {
        if (xb < 64) merge_chunks(xb);
        else samp_chunk(xb - 64, 96);                     // chunks 96..127
    } else if (s == 2) {
        if (xb < 1024) phaseC_comb(scores, xb * 4 + wid, 16, 16, tile);
        else samp_chunk(xb - 1024, 64);                   // chunks 64..95
    } else {
        if (xb < 512) phaseC_comb(scores, xb * 4 + wid, 8, 8, tile);
        else samp_chunk(xb - 512, 32);                    // chunks 32..63
    }
}

// ---------------- tail: last phaseC_comb band + hybrid composition ----------------
__global__ void k_tail(const float* __restrict__ scores)
{
    __shared__ float s_tile[4][32 * 33];
    if (blockIdx.x < 512) {
        phaseC_comb(scores, blockIdx.x * 4 + (threadIdx.x >> 5), 0, 8,
                    &s_tile[threadIdx.x >> 5][0]);
    } else {
        comp_hybrid(blockIdx.x - 512);   // 64 blocks, warp per b
    }
}

// ---------------- finalize ----------------
__global__ void k_final(float* __restrict__ out)
{
    int tid = blockIdx.x * blockDim.x + threadIdx.x;  // 0 .. 2^20-1
    int bz = tid >> 13;
    int rem = tid & 8191;
    int n = rem >> 1;
    int e = rem & 1;
    int be = bz * ENS + e;
    float s = (float)((g_bits[(size_t)be * (NN / 32) + (n >> 5)] >> (n & 31)) & 1u);
    float m = g_M[(size_t)be * NN + n] * __expf(g_off[be] - g_logZ[be]);
    out[tid] = (s - m) + m;
    out[HALF_OUT + tid] = m;
}

extern "C" void kernel_launch(void* const* d_in, const int* in_sizes, int n_in,
                              void* d_out, int out_size)
{
    const float* scores = (const float*)d_in[0];
    float* out = (float*)d_out;
    (void)in_sizes; (void)n_in; (void)out_size;

    k_slice<<<64 + 2048,        128>>>(scores, 0);  // backward + phaseA
    k_slice<<<64 + 64 + 2048,   128>>>(scores, 1);  // backward + merge + sc 96-127
    k_slice<<<64 + 1024 + 2048, 128>>>(scores, 2);  // backward + PC 16-31 + sc 64-95
    k_slice<<<64 + 512 + 2048,  128>>>(scores, 3);  // backward + PC 8-15  + sc 32-63
    k_tail<<<576, 128>>>(scores);                   // PC 0-7 + hybrid comp
    k_final<<<2048, 512>>>(out);
}